// round 4
// baseline (speedup 1.0000x reference)
#include <cuda_runtime.h>
#include <cstdint>

// LSTM: B=8192, T=128, I=32, H=64, OUT=8.
// gates = [x_t | h] @ Wcat + (b_ih+b_hh), Wcat[k][g]: k<32 -> W_ih[g][k], else W_hh[g][k-32]
// Per-CTA: 64 batch rows, full T loop locally. tf32 mma.sync m16n8k8,
// weights resident in registers, A tile (tf32) in padded smem.

#define B_TOT 8192
#define T_LEN 128
#define I_SZ  32
#define H_SZ  64
#define G_SZ  256      // 4*H
#define K_SZ  96       // I + H
#define OUT_SZ 8
#define M_BLK 64
#define PA    100      // A smem pitch in words (odd-ish mod 32 -> conflict-free frags)
#define NTHREADS 256

__device__ __forceinline__ uint32_t f2tf32(float f) {
    uint32_t r;
    asm("cvt.rna.tf32.f32 %0, %1;" : "=r"(r) : "f"(f));
    return r;
}

__device__ __forceinline__ void mma_tf32(float c[4],
                                         uint32_t a0, uint32_t a1, uint32_t a2, uint32_t a3,
                                         uint32_t b0, uint32_t b1) {
    asm("mma.sync.aligned.m16n8k8.row.col.f32.tf32.tf32.f32 "
        "{%0,%1,%2,%3},{%4,%5,%6,%7},{%8,%9},{%0,%1,%2,%3};"
        : "+f"(c[0]), "+f"(c[1]), "+f"(c[2]), "+f"(c[3])
        : "r"(a0), "r"(a1), "r"(a2), "r"(a3), "r"(b0), "r"(b1));
}

// accurate fast sigmoid: 1/(1+exp(-x)) via ex2.approx + rcp.approx (~1e-6 abs err)
__device__ __forceinline__ float sigf(float x) {
    float e = __expf(-x);
    return __fdividef(1.0f, 1.0f + e);
}
__device__ __forceinline__ float tanh_fast(float x) {
    return 2.0f * sigf(2.0f * x) - 1.0f;
}

__global__ __launch_bounds__(NTHREADS, 1)
void lstm_fused_kernel(const float* __restrict__ x,
                       const float* __restrict__ W_ih,
                       const float* __restrict__ W_hh,
                       const float* __restrict__ b_ih,
                       const float* __restrict__ b_hh,
                       const float* __restrict__ W_fc,
                       const float* __restrict__ b_fc,
                       float* __restrict__ out) {
    __shared__ __align__(16) uint32_t Asm[M_BLK * PA];  // tf32 A tile: cols 0..31 = x_t, 32..95 = h

    const int tid  = threadIdx.x;
    const int warp = tid >> 5;
    const int lane = tid & 31;
    const int row0 = blockIdx.x * M_BLK;
    const int colw = warp * 8;            // this warp's 8 h-columns

    // ---- B fragments (weights), resident in registers for all 128 steps ----
    // warp w, gate g covers gate-columns g*64 + colw .. +7
    // b0 = Wcat[q*8 + lane%4      ][gcol],  b1 = Wcat[q*8 + 4 + lane%4][gcol]
    uint32_t bfr[4][12][2];
    {
        const int bc = colw + (lane >> 2);            // n-index within warp tile
        #pragma unroll
        for (int g = 0; g < 4; ++g) {
            const int gc = g * 64 + bc;               // gate column 0..255
            #pragma unroll
            for (int q = 0; q < 12; ++q) {
                const int k0 = q * 8 + (lane & 3);
                const int k1 = k0 + 4;
                float w0 = (k0 < I_SZ) ? W_ih[gc * I_SZ + k0] : W_hh[gc * H_SZ + (k0 - I_SZ)];
                float w1 = (k1 < I_SZ) ? W_ih[gc * I_SZ + k1] : W_hh[gc * H_SZ + (k1 - I_SZ)];
                bfr[g][q][0] = f2tf32(w0);
                bfr[g][q][1] = f2tf32(w1);
            }
        }
    }

    // bias (exact fp32, added at accumulator init): cols colbase + 2*(lane%4) + {0,1}
    float bias2[4][2];
    {
        #pragma unroll
        for (int g = 0; g < 4; ++g) {
            const int c0 = g * 64 + colw + 2 * (lane & 3);
            bias2[g][0] = b_ih[c0] + b_hh[c0];
            bias2[g][1] = b_ih[c0 + 1] + b_hh[c0 + 1];
        }
    }

    // zero A tile (h0 = 0); barrier before anyone stages x over it
    for (int i = tid; i < M_BLK * PA; i += NTHREADS) Asm[i] = 0u;
    __syncthreads();

    // ---- x prefetch: each thread owns row tid/4, cols (tid%4)*8 .. +7 ----
    const int xrow = tid >> 2;
    const int xcol = (tid & 3) * 8;
    float xr[8];
    {
        const float* p = x + ((size_t)(row0 + xrow) * T_LEN + 0) * I_SZ + xcol;
        float4 a = *(const float4*)p;
        float4 b = *(const float4*)(p + 4);
        xr[0] = a.x; xr[1] = a.y; xr[2] = a.z; xr[3] = a.w;
        xr[4] = b.x; xr[5] = b.y; xr[6] = b.z; xr[7] = b.w;
    }

    float cst[4][4];
    #pragma unroll
    for (int r = 0; r < 4; ++r)
        #pragma unroll
        for (int e = 0; e < 4; ++e) cst[r][e] = 0.0f;

    const int arl = lane >> 2;   // frag row-in-group
    const int akl = lane & 3;    // frag k-in-group

    for (int t = 0; t < T_LEN; ++t) {
        // stage prefetched x_t into smem as tf32 (two STS.128 per thread)
        {
            uint32_t* ap = Asm + xrow * PA + xcol;
            uint4 v0 = make_uint4(f2tf32(xr[0]), f2tf32(xr[1]), f2tf32(xr[2]), f2tf32(xr[3]));
            uint4 v1 = make_uint4(f2tf32(xr[4]), f2tf32(xr[5]), f2tf32(xr[6]), f2tf32(xr[7]));
            *reinterpret_cast<uint4*>(ap)     = v0;
            *reinterpret_cast<uint4*>(ap + 4) = v1;
        }
        // prefetch x_{t+1} under the MMA phase
        if (t + 1 < T_LEN) {
            const float* p = x + ((size_t)(row0 + xrow) * T_LEN + (t + 1)) * I_SZ + xcol;
            float4 a = *(const float4*)p;
            float4 b = *(const float4*)(p + 4);
            xr[0] = a.x; xr[1] = a.y; xr[2] = a.z; xr[3] = a.w;
            xr[4] = b.x; xr[5] = b.y; xr[6] = b.z; xr[7] = b.w;
        }
        __syncthreads();   // x_t staged, h_{t-1} visible

        // ---- gates[64,256] = A[64,96] @ Wcat[96,256] + bias ----
        float acc[4][4][4];
        #pragma unroll
        for (int r = 0; r < 4; ++r)
            #pragma unroll
            for (int g = 0; g < 4; ++g) {
                acc[r][g][0] = bias2[g][0];
                acc[r][g][1] = bias2[g][1];
                acc[r][g][2] = bias2[g][0];
                acc[r][g][3] = bias2[g][1];
            }

        #pragma unroll
        for (int q = 0; q < 12; ++q) {
            #pragma unroll
            for (int r = 0; r < 4; ++r) {
                const int ar = r * 16 + arl;
                const int ak = q * 8 + akl;
                uint32_t a0 = Asm[ar * PA + ak];
                uint32_t a1 = Asm[(ar + 8) * PA + ak];
                uint32_t a2 = Asm[ar * PA + ak + 4];
                uint32_t a3 = Asm[(ar + 8) * PA + ak + 4];
                #pragma unroll
                for (int g = 0; g < 4; ++g)
                    mma_tf32(acc[r][g], a0, a1, a2, a3, bfr[g][q][0], bfr[g][q][1]);
            }
        }
        __syncthreads();   // all A reads done before h_t overwrite

        // ---- activations + state update; write h_t back as tf32 ----
        #pragma unroll
        for (int r = 0; r < 4; ++r) {
            float hv[4];
            #pragma unroll
            for (int e = 0; e < 4; ++e) {
                float ig = sigf(acc[r][0][e]);
                float fg = sigf(acc[r][1][e]);
                float gg = tanh_fast(acc[r][2][e]);
                float og = sigf(acc[r][3][e]);
                float c  = fg * cst[r][e] + ig * gg;
                cst[r][e] = c;
                hv[e] = og * tanh_fast(c);
            }
            const int hr = r * 16 + arl;
            uint32_t* hp = Asm + hr * PA + 32 + colw + 2 * (lane & 3);
            *reinterpret_cast<uint2*>(hp)          = make_uint2(f2tf32(hv[0]), f2tf32(hv[1]));
            *reinterpret_cast<uint2*>(hp + 8 * PA) = make_uint2(f2tf32(hv[2]), f2tf32(hv[3]));
        }
    }

    __syncthreads();   // final h_T (tf32) visible in Asm cols 32..95

    // ---- out[row, o] = h_T . W_fc[o] + b_fc[o]  (512 dots of length 64) ----
    for (int idx = tid; idx < M_BLK * OUT_SZ; idx += NTHREADS) {
        const int row = idx >> 3;
        const int o   = idx & 7;
        const float* wf = W_fc + o * H_SZ;
        const uint32_t* hp = Asm + row * PA + 32;
        float s = b_fc[o];
        #pragma unroll
        for (int k = 0; k < H_SZ; ++k)
            s += __uint_as_float(hp[k]) * wf[k];
        out[(size_t)(row0 + row) * OUT_SZ + o] = s;
    }
}

extern "C" void kernel_launch(void* const* d_in, const int* in_sizes, int n_in,
                              void* d_out, int out_size) {
    const float* x    = (const float*)d_in[0];
    const float* W_ih = (const float*)d_in[1];
    const float* W_hh = (const float*)d_in[2];
    const float* b_ih = (const float*)d_in[3];
    const float* b_hh = (const float*)d_in[4];
    const float* W_fc = (const float*)d_in[5];
    const float* b_fc = (const float*)d_in[6];
    float* out = (float*)d_out;

    lstm_fused_kernel<<<B_TOT / M_BLK, NTHREADS>>>(x, W_ih, W_hh, b_ih, b_hh, W_fc, b_fc, out);
}